// round 13
// baseline (speedup 1.0000x reference)
#include <cuda_runtime.h>
#include <cuda_fp16.h>

// Critic_66511863546286 — folded attention critic, round 13.
// B=256, S=1024, H=256, feat dims = 2, 3 iterations.
// R13 = R9's inner math (f=1/4 poly fraction — the confirmed optimum —
// single accumulator per point) restructured to 1 point/thread with
// block=1024: loaded SMs go from 8 -> 16 warps/SMSP to close the ~40%
// idle-issue gap. Registers forced <=32 via __launch_bounds__(1024,2).
// LDS wavefronts double (31% -> ~60%, still under cap).

#define NB 256
#define NS 1024
#define NH 256
#define NHP 128   // h-pairs
#define K3 768
#define NITER 3
#define NFC 20
#define BT 1024   // one sequence point per thread

// Precomputed fused coefficients (natural scale, f32 masters).
__device__ float4 gABp[NH];  // (A0, A1, B0, B1) per h
__device__ float4 gCdv[NH];  // (C0, C1, d, v[h])
__device__ float2 gF[NFC];   // fc1_w · sw
__device__ float  gfb[NFC];  // fc1_w · sb + fc1_b

__device__ __forceinline__ float ex2_approx(float x) {
    float y; asm("ex2.approx.f32 %0, %1;" : "=f"(y) : "f"(x)); return y;
}
__device__ __forceinline__ unsigned hfma2u(unsigned a, unsigned b, unsigned c) {
    unsigned d;
    asm("fma.rn.f16x2 %0, %1, %2, %3;" : "=r"(d) : "r"(a), "r"(b), "r"(c));
    return d;
}
__device__ __forceinline__ unsigned hmul2u(unsigned a, unsigned b) {
    unsigned d;
    asm("mul.rn.f16x2 %0, %1, %2;" : "=r"(d) : "r"(a), "r"(b));
    return d;
}
__device__ __forceinline__ unsigned tanh16x2(unsigned x) {
    unsigned y; asm("tanh.approx.f16x2 %0, %1;" : "=r"(y) : "r"(x)); return y;
}
__device__ __forceinline__ unsigned f2h2(float a, float b) {
    __half2 h = __floats2half2_rn(a, b);
    return *reinterpret_cast<unsigned*>(&h);
}
__device__ __forceinline__ float h2sum(unsigned u) {
    __half2 h = *reinterpret_cast<__half2*>(&u);
    float2 f = __half22float2(h);
    return f.x + f.y;
}

// ---------------------------------------------------------------------------
// Precompute: fold W through the 1x1-conv encoders (f32 masters).
// ---------------------------------------------------------------------------
__global__ void precompute_kernel(
    const float* __restrict__ sw, const float* __restrict__ sb,
    const float* __restrict__ dw, const float* __restrict__ db,
    const float* __restrict__ W,  const float* __restrict__ v,
    const float* __restrict__ fc1_w, const float* __restrict__ fc1_b)
{
    __shared__ float sred[8][8];
    int tid = threadIdx.x;
    int blk = blockIdx.x;
    int lane = tid & 31, w = tid >> 5;

    if (blk < NH) {
        int h = blk;
        float ws = W[h * K3 + tid];
        float wd = W[h * K3 + 256 + tid];
        float wc = W[h * K3 + 512 + tid];
        float s0 = sw[tid * 2 + 0], s1 = sw[tid * 2 + 1];
        float sbk = sb[tid];
        float p[7];
        p[0] = ws * s0;
        p[1] = ws * s1;
        p[2] = wd * dw[tid * 2 + 0];
        p[3] = wd * dw[tid * 2 + 1];
        p[4] = wc * s0;
        p[5] = wc * s1;
        p[6] = ws * sbk + wd * db[tid] + wc * sbk;
        #pragma unroll
        for (int o = 16; o > 0; o >>= 1)
            #pragma unroll
            for (int i = 0; i < 7; i++)
                p[i] += __shfl_xor_sync(0xffffffffu, p[i], o);
        if (lane == 0) {
            #pragma unroll
            for (int i = 0; i < 7; i++) sred[w][i] = p[i];
        }
        __syncthreads();
        if (tid == 0) {
            float q[7];
            #pragma unroll
            for (int i = 0; i < 7; i++) {
                q[i] = 0.f;
                for (int ww = 0; ww < 8; ww++) q[i] += sred[ww][i];
            }
            gABp[h] = make_float4(q[0], q[1], q[2], q[3]);
            gCdv[h] = make_float4(q[4], q[5], q[6], v[h]);
        }
    } else {
        int j = blk - NH;
        float fw = fc1_w[j * NH + tid];
        float p0 = fw * sw[tid * 2 + 0];
        float p1 = fw * sw[tid * 2 + 1];
        float p2 = fw * sb[tid];
        #pragma unroll
        for (int o = 16; o > 0; o >>= 1) {
            p0 += __shfl_xor_sync(0xffffffffu, p0, o);
            p1 += __shfl_xor_sync(0xffffffffu, p1, o);
            p2 += __shfl_xor_sync(0xffffffffu, p2, o);
        }
        if (lane == 0) { sred[w][0] = p0; sred[w][1] = p1; sred[w][2] = p2; }
        __syncthreads();
        if (tid == 0) {
            float q0 = 0.f, q1 = 0.f, q2 = 0.f;
            for (int ww = 0; ww < 8; ww++) {
                q0 += sred[ww][0]; q1 += sred[ww][1]; q2 += sred[ww][2];
            }
            gF[j] = make_float2(q0, q1);
            gfb[j] = q2 + fc1_b[j];
        }
    }
}

// ---------------------------------------------------------------------------
// Main kernel: one block per batch; 1024 threads; ONE point per thread.
// h in f16x2 pairs; 3/4 MUFU tanh, 1/4 FMA-pipe quintic (R9 optimum).
// ---------------------------------------------------------------------------
__global__ void __launch_bounds__(BT, 2)
attn_kernel(const float* __restrict__ stat, const float* __restrict__ dyn,
            const float* __restrict__ istate,
            const float* __restrict__ fc2_w, const float* __restrict__ fc2_b,
            float* __restrict__ out)
{
    __shared__ uint4 sC[NHP];        // (A0pair, A1pair, B0pair, B1pair) half2s
    __shared__ uint2 sGV[NHP];       // (g-pair, v-pair) half2s, g rewritten/iter
    __shared__ float4 sCdv[NH];      // (C0,C1,d,v) f32
    __shared__ float sredM[32], sredP[32], sredX[32], sredY[32];
    __shared__ float bc[4];

    const float LOG2E = 1.4426950408889634f;
    int b = blockIdx.x;
    int s = threadIdx.x;              // 0..1023
    int lane = s & 31, warp = s >> 5;

    // odd-quintic tanh: tanh(x) ~= x*(1 + x2*(PA + PB*x2))
    const unsigned PA2 = f2h2(-0.3248f, -0.3248f);
    const unsigned PB2 = f2h2(0.0864f, 0.0864f);
    const unsigned ONE2 = f2h2(1.0f, 1.0f);

    // features for point s (f32 masters kept for the softmax stage)
    float x0 = stat[b * 2 * NS + s];
    float x1 = stat[b * 2 * NS + NS + s];
    float y0 = dyn[b * 2 * NS + s];
    float y1 = dyn[b * 2 * NS + NS + s];
    unsigned x02 = f2h2(x0, x0), x12 = f2h2(x1, x1);
    unsigned y02 = f2h2(y0, y0), y12 = f2h2(y1, y1);

    if (s < NH) sCdv[s] = gCdv[s];
    if (s < NHP) {
        float4 pa = gABp[2 * s];
        float4 pb = gABp[2 * s + 1];
        sC[s] = make_uint4(f2h2(pa.x, pb.x), f2h2(pa.y, pb.y),
                           f2h2(pa.z, pb.z), f2h2(pa.w, pb.w));
    }

    float z0 = istate[b * 2 + 0];
    float z1 = istate[b * 2 + 1];

    for (int it = 0; it < NITER; it++) {
        __syncthreads();
        if (s < NHP) {
            float4 ca = sCdv[2 * s];
            float4 cb = sCdv[2 * s + 1];
            float ga = fmaf(ca.x, z0, fmaf(ca.y, z1, ca.z));
            float gb = fmaf(cb.x, z0, fmaf(cb.y, z1, cb.z));
            sGV[s] = make_uint2(f2h2(ga, gb), f2h2(ca.w, cb.w));
        }
        __syncthreads();

        // score: t = sum over h-pairs of (v,v') * tanh(A·x + B·y + (g,g'))
        // j%4==3 -> FMA-pipe quintic; else MUFU tanh16x2.
        float t = 0.f;
        #pragma unroll
        for (int kc = 0; kc < NHP / 16; kc++) {
            unsigned acc = 0u;           // half2 (0,0)
            #pragma unroll
            for (int j = 0; j < 16; j++) {
                int k = kc * 16 + j;
                uint4 cc = sC[k];        // LDS.128
                uint2 gv = sGV[k];       // LDS.64

                unsigned arg = hfma2u(cc.x, x02, gv.x);
                arg = hfma2u(cc.y, x12, arg);
                arg = hfma2u(cc.z, y02, arg);
                arg = hfma2u(cc.w, y12, arg);

                unsigned th;
                if ((j & 3) == 3) {
                    unsigned x2 = hmul2u(arg, arg);
                    unsigned u  = hfma2u(x2, PB2, PA2);
                    unsigned w  = hfma2u(u, x2, ONE2);
                    th = hmul2u(w, arg);
                } else {
                    th = tanh16x2(arg);
                }
                acc = hfma2u(gv.y, th, acc);
            }
            t += h2sum(acc);
        }

        // block max over S=1024
        float m = t;
        #pragma unroll
        for (int o = 16; o > 0; o >>= 1)
            m = fmaxf(m, __shfl_xor_sync(0xffffffffu, m, o));
        if (lane == 0) sredM[warp] = m;
        __syncthreads();
        if (s < 32) {
            float mm = sredM[s];
            #pragma unroll
            for (int o = 16; o > 0; o >>= 1)
                mm = fmaxf(mm, __shfl_xor_sync(0xffffffffu, mm, o));
            if (s == 0) bc[0] = mm;
        }
        __syncthreads();
        float M = bc[0];

        // softmax weight + weighted feature sums (f32)
        float p = ex2_approx((t - M) * LOG2E);
        float a = p, bx = p * x0, by = p * x1;
        #pragma unroll
        for (int o = 16; o > 0; o >>= 1) {
            a  += __shfl_xor_sync(0xffffffffu, a,  o);
            bx += __shfl_xor_sync(0xffffffffu, bx, o);
            by += __shfl_xor_sync(0xffffffffu, by, o);
        }
        if (lane == 0) { sredP[warp] = a; sredX[warp] = bx; sredY[warp] = by; }
        __syncthreads();
        if (s < 32) {
            float aa = sredP[s], xx = sredX[s], yy = sredY[s];
            #pragma unroll
            for (int o = 16; o > 0; o >>= 1) {
                aa += __shfl_xor_sync(0xffffffffu, aa, o);
                xx += __shfl_xor_sync(0xffffffffu, xx, o);
                yy += __shfl_xor_sync(0xffffffffu, yy, o);
            }
            if (s == 0) { bc[1] = aa; bc[2] = xx; bc[3] = yy; }
        }
        __syncthreads();
        float inv = 1.f / bc[1];
        z0 = bc[2] * inv;   // xbar0
        z1 = bc[3] * inv;   // xbar1
    }

    // Output MLP (folded through sw), f32
    if (s == 0) {
        float o = fc2_b[0];
        #pragma unroll
        for (int j = 0; j < NFC; j++) {
            float hv = fmaf(gF[j].x, z0, fmaf(gF[j].y, z1, gfb[j]));
            hv = fmaxf(hv, 0.f);
            o = fmaf(fc2_w[j], hv, o);
        }
        out[b] = o;
    }
}

extern "C" void kernel_launch(void* const* d_in, const int* in_sizes, int n_in,
                              void* d_out, int out_size)
{
    const float* stat   = (const float*)d_in[0];   // [256, 2, 1024]
    const float* dyn    = (const float*)d_in[1];   // [256, 2, 1024]
    const float* istate = (const float*)d_in[2];   // [256, 2]
    const float* sw     = (const float*)d_in[3];   // [256, 2]
    const float* sb     = (const float*)d_in[4];   // [256]
    const float* dw     = (const float*)d_in[5];   // [256, 2]
    const float* db     = (const float*)d_in[6];   // [256]
    const float* v      = (const float*)d_in[7];   // [1, 256]
    const float* W      = (const float*)d_in[8];   // [256, 768]
    const float* fc1_w  = (const float*)d_in[9];   // [20, 256]
    const float* fc1_b  = (const float*)d_in[10];  // [20]
    const float* fc2_w  = (const float*)d_in[11];  // [1, 20]
    const float* fc2_b  = (const float*)d_in[12];  // [1]
    float* out = (float*)d_out;                    // [256, 1]

    precompute_kernel<<<NH + NFC, 256>>>(sw, sb, dw, db, W, v, fc1_w, fc1_b);
    attn_kernel<<<NB, BT>>>(stat, dyn, istate, fc2_w, fc2_b, out);
}

// round 14
// speedup vs baseline: 1.2877x; 1.2877x over previous
#include <cuda_runtime.h>
#include <cuda_fp16.h>

// Critic_66511863546286 — folded attention critic, round 14.
// B=256, S=1024, H=256, feat dims = 2, 3 iterations.
// R14: the affine arg computation args[S,H] = U[S,4] @ C[4,H] + g[H] moves
// to the tensor pipe via mma.sync.m16n8k8.f16 (A = 16 points x 8 feats
// (4 padded), B = feats x 8 h, C init = g). D fragment = half2 of 2 adjacent
// h for one point -> feeds tanh16x2 with no repacking. FMA pipe now only
// does v-accumulate + poly-tanh, so poly fraction rises to f=1/2
// (alternate h-tiles). Scores land in a shared array; R9's proven softmax
// stage runs verbatim.

#define NB 256
#define NS 1024
#define NH 256
#define K3 768
#define NITER 3
#define NFC 20
#define BT 512    // threads/block; thread t owns points t (lo) and t+512 (hi)

// Precomputed fused coefficients (natural scale, f32 masters).
__device__ float4 gABp[NH];  // (A0, A1, B0, B1) per h
__device__ float4 gCdv[NH];  // (C0, C1, d, v[h])
__device__ float2 gF[NFC];   // fc1_w · sw
__device__ float  gfb[NFC];  // fc1_w · sb + fc1_b

__device__ __forceinline__ float ex2_approx(float x) {
    float y; asm("ex2.approx.f32 %0, %1;" : "=f"(y) : "f"(x)); return y;
}
__device__ __forceinline__ unsigned hfma2u(unsigned a, unsigned b, unsigned c) {
    unsigned d;
    asm("fma.rn.f16x2 %0, %1, %2, %3;" : "=r"(d) : "r"(a), "r"(b), "r"(c));
    return d;
}
__device__ __forceinline__ unsigned hmul2u(unsigned a, unsigned b) {
    unsigned d;
    asm("mul.rn.f16x2 %0, %1, %2;" : "=r"(d) : "r"(a), "r"(b));
    return d;
}
__device__ __forceinline__ unsigned tanh16x2(unsigned x) {
    unsigned y; asm("tanh.approx.f16x2 %0, %1;" : "=r"(y) : "r"(x)); return y;
}
__device__ __forceinline__ unsigned f2h2(float a, float b) {
    __half2 h = __floats2half2_rn(a, b);
    return *reinterpret_cast<unsigned*>(&h);
}
__device__ __forceinline__ float h2sum(unsigned u) {
    __half2 h = *reinterpret_cast<__half2*>(&u);
    float2 f = __half22float2(h);
    return f.x + f.y;
}
// D(16x8) = A(16x8) * B(8x8) + C ; f16 in/out. A: 2 regs, B: 1, C/D: 2.
__device__ __forceinline__ void mma16n8k8(unsigned& d0, unsigned& d1,
    unsigned a0, unsigned a1, unsigned b0, unsigned c0, unsigned c1) {
    asm("mma.sync.aligned.m16n8k8.row.col.f16.f16.f16.f16 "
        "{%0,%1}, {%2,%3}, {%4}, {%5,%6};"
        : "=r"(d0), "=r"(d1)
        : "r"(a0), "r"(a1), "r"(b0), "r"(c0), "r"(c1));
}

// ---------------------------------------------------------------------------
// Precompute: fold W through the 1x1-conv encoders (f32 masters).
// ---------------------------------------------------------------------------
__global__ void precompute_kernel(
    const float* __restrict__ sw, const float* __restrict__ sb,
    const float* __restrict__ dw, const float* __restrict__ db,
    const float* __restrict__ W,  const float* __restrict__ v,
    const float* __restrict__ fc1_w, const float* __restrict__ fc1_b)
{
    __shared__ float sred[8][8];
    int tid = threadIdx.x;
    int blk = blockIdx.x;
    int lane = tid & 31, w = tid >> 5;

    if (blk < NH) {
        int h = blk;
        float ws = W[h * K3 + tid];
        float wd = W[h * K3 + 256 + tid];
        float wc = W[h * K3 + 512 + tid];
        float s0 = sw[tid * 2 + 0], s1 = sw[tid * 2 + 1];
        float sbk = sb[tid];
        float p[7];
        p[0] = ws * s0;
        p[1] = ws * s1;
        p[2] = wd * dw[tid * 2 + 0];
        p[3] = wd * dw[tid * 2 + 1];
        p[4] = wc * s0;
        p[5] = wc * s1;
        p[6] = ws * sbk + wd * db[tid] + wc * sbk;
        #pragma unroll
        for (int o = 16; o > 0; o >>= 1)
            #pragma unroll
            for (int i = 0; i < 7; i++)
                p[i] += __shfl_xor_sync(0xffffffffu, p[i], o);
        if (lane == 0) {
            #pragma unroll
            for (int i = 0; i < 7; i++) sred[w][i] = p[i];
        }
        __syncthreads();
        if (tid == 0) {
            float q[7];
            #pragma unroll
            for (int i = 0; i < 7; i++) {
                q[i] = 0.f;
                for (int ww = 0; ww < 8; ww++) q[i] += sred[ww][i];
            }
            gABp[h] = make_float4(q[0], q[1], q[2], q[3]);
            gCdv[h] = make_float4(q[4], q[5], q[6], v[h]);
        }
    } else {
        int j = blk - NH;
        float fw = fc1_w[j * NH + tid];
        float p0 = fw * sw[tid * 2 + 0];
        float p1 = fw * sw[tid * 2 + 1];
        float p2 = fw * sb[tid];
        #pragma unroll
        for (int o = 16; o > 0; o >>= 1) {
            p0 += __shfl_xor_sync(0xffffffffu, p0, o);
            p1 += __shfl_xor_sync(0xffffffffu, p1, o);
            p2 += __shfl_xor_sync(0xffffffffu, p2, o);
        }
        if (lane == 0) { sred[w][0] = p0; sred[w][1] = p1; sred[w][2] = p2; }
        __syncthreads();
        if (tid == 0) {
            float q0 = 0.f, q1 = 0.f, q2 = 0.f;
            for (int ww = 0; ww < 8; ww++) {
                q0 += sred[ww][0]; q1 += sred[ww][1]; q2 += sred[ww][2];
            }
            gF[j] = make_float2(q0, q1);
            gfb[j] = q2 + fc1_b[j];
        }
    }
}

// ---------------------------------------------------------------------------
// Main kernel: one block per batch; 512 threads; warp w owns points
// [64w, 64w+64) for the MMA stage; thread t owns points t, t+512 for the
// softmax stage (scores passed through shared sScore).
// ---------------------------------------------------------------------------
__global__ void __launch_bounds__(BT, 2)
attn_kernel(const float* __restrict__ stat, const float* __restrict__ dyn,
            const float* __restrict__ istate,
            const float* __restrict__ fc2_w, const float* __restrict__ fc2_b,
            float* __restrict__ out)
{
    __shared__ uint2 sU[NS];         // per-point features {(x0,x1),(y0,y1)} f16
    __shared__ unsigned sBf[NH * 4]; // per-h B-frag half2s {(A0,A1),(B0,B1),0,0}
    __shared__ uint2 sGV[NH / 2];    // per h-pair {(g,g'), (v,v')} f16
    __shared__ float4 sCdv[NH];      // (C0,C1,d,v) f32
    __shared__ float sScore[NS];     // scores handoff
    __shared__ float sredM[16], sredP[16], sredX[16], sredY[16];
    __shared__ float bc[4];

    const float LOG2E = 1.4426950408889634f;
    int b = blockIdx.x;
    int s = threadIdx.x;              // 0..511
    int lane = s & 31, warp = s >> 5;
    int gid = lane >> 2, tig = lane & 3;

    // odd-quintic tanh: tanh(x) ~= x*(1 + x2*(PA + PB*x2))
    const unsigned PA2 = f2h2(-0.3248f, -0.3248f);
    const unsigned PB2 = f2h2(0.0864f, 0.0864f);
    const unsigned ONE2 = f2h2(1.0f, 1.0f);

    // features for points s (lo) and s+512 (hi); f32 masters for softmax
    float x0l = stat[b * 2 * NS + s],      x0h = stat[b * 2 * NS + s + BT];
    float x1l = stat[b * 2 * NS + NS + s], x1h = stat[b * 2 * NS + NS + s + BT];
    float y0l = dyn[b * 2 * NS + s],       y0h = dyn[b * 2 * NS + s + BT];
    float y1l = dyn[b * 2 * NS + NS + s],  y1h = dyn[b * 2 * NS + NS + s + BT];

    // shared feature table (f16) for A-fragments
    sU[s]      = make_uint2(f2h2(x0l, x1l), f2h2(y0l, y1l));
    sU[s + BT] = make_uint2(f2h2(x0h, x1h), f2h2(y0h, y1h));

    if (s < NH) {
        sCdv[s] = gCdv[s];
        float4 q = gABp[s];
        sBf[s * 4 + 0] = f2h2(q.x, q.y);   // (A0, A1)
        sBf[s * 4 + 1] = f2h2(q.z, q.w);   // (B0, B1)
        sBf[s * 4 + 2] = 0u;               // k-pad
        sBf[s * 4 + 3] = 0u;
    }
    __syncthreads();

    // A fragments: constant across iterations and h-tiles.
    // pt-tile p covers points warp*64 + p*16 + {0..15}.
    unsigned a01[4], a23[4];
    #pragma unroll
    for (int p = 0; p < 4; p++) {
        int pt0 = (warp << 6) + (p << 4) + gid;
        uint2 F0 = sU[pt0];
        uint2 F1 = sU[pt0 + 8];
        a01[p] = (tig == 0) ? F0.x : (tig == 1) ? F0.y : 0u;
        a23[p] = (tig == 0) ? F1.x : (tig == 1) ? F1.y : 0u;
    }

    float z0 = istate[b * 2 + 0];
    float z1 = istate[b * 2 + 1];

    for (int it = 0; it < NITER; it++) {
        __syncthreads();
        if (s < NH / 2) {
            float4 ca = sCdv[2 * s];
            float4 cb = sCdv[2 * s + 1];
            float ga = fmaf(ca.x, z0, fmaf(ca.y, z1, ca.z));
            float gb = fmaf(cb.x, z0, fmaf(cb.y, z1, cb.z));
            sGV[s] = make_uint2(f2h2(ga, gb), f2h2(ca.w, cb.w));
        }
        __syncthreads();

        // MMA mainloop: 32 h-tiles of 8 h; 4 pt-tiles of 16 points per warp.
        // Even h-tiles: MUFU tanh16x2; odd h-tiles: FMA-pipe quintic (f=1/2).
        float accf[8];
        #pragma unroll
        for (int i = 0; i < 8; i++) accf[i] = 0.f;

        #pragma unroll
        for (int hc = 0; hc < 4; hc++) {
            unsigned acch[8];
            #pragma unroll
            for (int i = 0; i < 8; i++) acch[i] = 0u;
            #pragma unroll
            for (int hj = 0; hj < 8; hj++) {
                int ht = hc * 8 + hj;
                unsigned bf = sBf[((ht << 3) + gid) * 4 + tig]; // B frag
                uint2 gv = sGV[(ht << 2) + tig];  // {(g,g'), (v,v')} for cols 2tig
                #pragma unroll
                for (int p = 0; p < 4; p++) {
                    unsigned d0, d1;
                    mma16n8k8(d0, d1, a01[p], a23[p], bf, gv.x, gv.x);
                    unsigned th0, th1;
                    if (ht & 1) {
                        unsigned x20 = hmul2u(d0, d0);
                        unsigned u0  = hfma2u(x20, PB2, PA2);
                        unsigned w0  = hfma2u(u0, x20, ONE2);
                        th0 = hmul2u(w0, d0);
                        unsigned x21 = hmul2u(d1, d1);
                        unsigned u1  = hfma2u(x21, PB2, PA2);
                        unsigned w1  = hfma2u(u1, x21, ONE2);
                        th1 = hmul2u(w1, d1);
                    } else {
                        th0 = tanh16x2(d0);
                        th1 = tanh16x2(d1);
                    }
                    acch[2 * p]     = hfma2u(gv.y, th0, acch[2 * p]);
                    acch[2 * p + 1] = hfma2u(gv.y, th1, acch[2 * p + 1]);
                }
            }
            #pragma unroll
            for (int i = 0; i < 8; i++) accf[i] += h2sum(acch[i]);
        }

        // reduce across the 4 threads of each group (different h columns)
        #pragma unroll
        for (int i = 0; i < 8; i++) {
            accf[i] += __shfl_xor_sync(0xffffffffu, accf[i], 1);
            accf[i] += __shfl_xor_sync(0xffffffffu, accf[i], 2);
        }
        if (tig == 0) {
            #pragma unroll
            for (int p = 0; p < 4; p++) {
                sScore[(warp << 6) + (p << 4) + gid]     = accf[2 * p];
                sScore[(warp << 6) + (p << 4) + gid + 8] = accf[2 * p + 1];
            }
        }
        __syncthreads();

        float t0 = sScore[s];
        float t1 = sScore[s + BT];

        // ---- R9 softmax stage (verbatim) ----
        float m = fmaxf(t0, t1);
        #pragma unroll
        for (int o = 16; o > 0; o >>= 1)
            m = fmaxf(m, __shfl_xor_sync(0xffffffffu, m, o));
        if (lane == 0) sredM[warp] = m;
        __syncthreads();
        if (s < 16) {
            float mm = sredM[s];
            #pragma unroll
            for (int o = 8; o > 0; o >>= 1)
                mm = fmaxf(mm, __shfl_xor_sync(0xffffu, mm, o));
            if (s == 0) bc[0] = mm;
        }
        __syncthreads();
        float M = bc[0];

        float p0 = ex2_approx((t0 - M) * LOG2E);
        float p1 = ex2_approx((t1 - M) * LOG2E);
        float a  = p0 + p1;
        float bx = fmaf(p0, x0l, p1 * x0h);
        float by = fmaf(p0, x1l, p1 * x1h);
        #pragma unroll
        for (int o = 16; o > 0; o >>= 1) {
            a  += __shfl_xor_sync(0xffffffffu, a,  o);
            bx += __shfl_xor_sync(0xffffffffu, bx, o);
            by += __shfl_xor_sync(0xffffffffu, by, o);
        }
        if (lane == 0) { sredP[warp] = a; sredX[warp] = bx; sredY[warp] = by; }
        __syncthreads();
        if (s < 16) {
            float aa = sredP[s], xx = sredX[s], yy = sredY[s];
            #pragma unroll
            for (int o = 8; o > 0; o >>= 1) {
                aa += __shfl_xor_sync(0xffffu, aa, o);
                xx += __shfl_xor_sync(0xffffu, xx, o);
                yy += __shfl_xor_sync(0xffffu, yy, o);
            }
            if (s == 0) { bc[1] = aa; bc[2] = xx; bc[3] = yy; }
        }
        __syncthreads();
        float inv = 1.f / bc[1];
        z0 = bc[2] * inv;   // xbar0
        z1 = bc[3] * inv;   // xbar1
    }

    // Output MLP (folded through sw), f32
    if (s == 0) {
        float o = fc2_b[0];
        #pragma unroll
        for (int j = 0; j < NFC; j++) {
            float hv = fmaf(gF[j].x, z0, fmaf(gF[j].y, z1, gfb[j]));
            hv = fmaxf(hv, 0.f);
            o = fmaf(fc2_w[j], hv, o);
        }
        out[b] = o;
    }
}

extern "C" void kernel_launch(void* const* d_in, const int* in_sizes, int n_in,
                              void* d_out, int out_size)
{
    const float* stat   = (const float*)d_in[0];   // [256, 2, 1024]
    const float* dyn    = (const float*)d_in[1];   // [256, 2, 1024]
    const float* istate = (const float*)d_in[2];   // [256, 2]
    const float* sw     = (const float*)d_in[3];   // [256, 2]
    const float* sb     = (const float*)d_in[4];   // [256]
    const float* dw     = (const float*)d_in[5];   // [256, 2]
    const float* db     = (const float*)d_in[6];   // [256]
    const float* v      = (const float*)d_in[7];   // [1, 256]
    const float* W      = (const float*)d_in[8];   // [256, 768]
    const float* fc1_w  = (const float*)d_in[9];   // [20, 256]
    const float* fc1_b  = (const float*)d_in[10];  // [20]
    const float* fc2_w  = (const float*)d_in[11];  // [1, 20]
    const float* fc2_b  = (const float*)d_in[12];  // [1]
    float* out = (float*)d_out;                    // [256, 1]

    precompute_kernel<<<NH + NFC, 256>>>(sw, sb, dw, db, W, v, fc1_w, fc1_b);
    attn_kernel<<<NB, BT>>>(stat, dyn, istate, fc2_w, fc2_b, out);
}

// round 15
// speedup vs baseline: 1.3250x; 1.0290x over previous
#include <cuda_runtime.h>
#include <cuda_fp16.h>

// Critic_66511863546286 — folded attention critic, round 15.
// B=256, S=1024, H=256, feat dims = 2, 3 iterations.
// R15 = R14 + (a) v-accumulation ALSO on the tensor pipe: the m16n8k8
// D-fragment layout equals its A-fragment layout, so tanh'd fragments chain
// into score += th @ (v (x) e0) with f32 accumulators — kills the acc-HFMA2s,
// the h2sum flushes, and the cross-thread shuffle reduce, and upgrades the
// cross-h accumulation to f32; (b) poly fraction 1/2 -> 3/4 (MUFU only on
// ht%4==0): MUFU ~1024 ~ FMA ~1536 ~ tensor ~1520 cyc/warp-iter, balanced.

#define NB 256
#define NS 1024
#define NH 256
#define K3 768
#define NITER 3
#define NFC 20
#define BT 512    // threads/block; thread t owns points t (lo) and t+512 (hi)

// Precomputed fused coefficients (natural scale, f32 masters).
__device__ float4 gABp[NH];  // (A0, A1, B0, B1) per h
__device__ float4 gCdv[NH];  // (C0, C1, d, v[h])
__device__ float2 gF[NFC];   // fc1_w · sw
__device__ float  gfb[NFC];  // fc1_w · sb + fc1_b

__device__ __forceinline__ float ex2_approx(float x) {
    float y; asm("ex2.approx.f32 %0, %1;" : "=f"(y) : "f"(x)); return y;
}
__device__ __forceinline__ unsigned hfma2u(unsigned a, unsigned b, unsigned c) {
    unsigned d;
    asm("fma.rn.f16x2 %0, %1, %2, %3;" : "=r"(d) : "r"(a), "r"(b), "r"(c));
    return d;
}
__device__ __forceinline__ unsigned hmul2u(unsigned a, unsigned b) {
    unsigned d;
    asm("mul.rn.f16x2 %0, %1, %2;" : "=r"(d) : "r"(a), "r"(b));
    return d;
}
__device__ __forceinline__ unsigned tanh16x2(unsigned x) {
    unsigned y; asm("tanh.approx.f16x2 %0, %1;" : "=r"(y) : "r"(x)); return y;
}
__device__ __forceinline__ unsigned f2h2(float a, float b) {
    __half2 h = __floats2half2_rn(a, b);
    return *reinterpret_cast<unsigned*>(&h);
}
// D(16x8) = A(16x8) * B(8x8) + C ; all f16. A: 2 regs, B: 1, C/D: 2.
__device__ __forceinline__ void mma16n8k8(unsigned& d0, unsigned& d1,
    unsigned a0, unsigned a1, unsigned b0, unsigned c0, unsigned c1) {
    asm("mma.sync.aligned.m16n8k8.row.col.f16.f16.f16.f16 "
        "{%0,%1}, {%2,%3}, {%4}, {%5,%6};"
        : "=r"(d0), "=r"(d1)
        : "r"(a0), "r"(a1), "r"(b0), "r"(c0), "r"(c1));
}
// D(16x8,f32) = A(16x8,f16) * B(8x8,f16) + C(f32). C/D: 4 f32 regs.
__device__ __forceinline__ void mma16n8k8_f32(float* c,
    unsigned a0, unsigned a1, unsigned b0) {
    asm("mma.sync.aligned.m16n8k8.row.col.f32.f16.f16.f32 "
        "{%0,%1,%2,%3}, {%4,%5}, {%6}, {%0,%1,%2,%3};"
        : "+f"(c[0]), "+f"(c[1]), "+f"(c[2]), "+f"(c[3])
        : "r"(a0), "r"(a1), "r"(b0));
}

// ---------------------------------------------------------------------------
// Precompute: fold W through the 1x1-conv encoders (f32 masters).
// ---------------------------------------------------------------------------
__global__ void precompute_kernel(
    const float* __restrict__ sw, const float* __restrict__ sb,
    const float* __restrict__ dw, const float* __restrict__ db,
    const float* __restrict__ W,  const float* __restrict__ v,
    const float* __restrict__ fc1_w, const float* __restrict__ fc1_b)
{
    __shared__ float sred[8][8];
    int tid = threadIdx.x;
    int blk = blockIdx.x;
    int lane = tid & 31, w = tid >> 5;

    if (blk < NH) {
        int h = blk;
        float ws = W[h * K3 + tid];
        float wd = W[h * K3 + 256 + tid];
        float wc = W[h * K3 + 512 + tid];
        float s0 = sw[tid * 2 + 0], s1 = sw[tid * 2 + 1];
        float sbk = sb[tid];
        float p[7];
        p[0] = ws * s0;
        p[1] = ws * s1;
        p[2] = wd * dw[tid * 2 + 0];
        p[3] = wd * dw[tid * 2 + 1];
        p[4] = wc * s0;
        p[5] = wc * s1;
        p[6] = ws * sbk + wd * db[tid] + wc * sbk;
        #pragma unroll
        for (int o = 16; o > 0; o >>= 1)
            #pragma unroll
            for (int i = 0; i < 7; i++)
                p[i] += __shfl_xor_sync(0xffffffffu, p[i], o);
        if (lane == 0) {
            #pragma unroll
            for (int i = 0; i < 7; i++) sred[w][i] = p[i];
        }
        __syncthreads();
        if (tid == 0) {
            float q[7];
            #pragma unroll
            for (int i = 0; i < 7; i++) {
                q[i] = 0.f;
                for (int ww = 0; ww < 8; ww++) q[i] += sred[ww][i];
            }
            gABp[h] = make_float4(q[0], q[1], q[2], q[3]);
            gCdv[h] = make_float4(q[4], q[5], q[6], v[h]);
        }
    } else {
        int j = blk - NH;
        float fw = fc1_w[j * NH + tid];
        float p0 = fw * sw[tid * 2 + 0];
        float p1 = fw * sw[tid * 2 + 1];
        float p2 = fw * sb[tid];
        #pragma unroll
        for (int o = 16; o > 0; o >>= 1) {
            p0 += __shfl_xor_sync(0xffffffffu, p0, o);
            p1 += __shfl_xor_sync(0xffffffffu, p1, o);
            p2 += __shfl_xor_sync(0xffffffffu, p2, o);
        }
        if (lane == 0) { sred[w][0] = p0; sred[w][1] = p1; sred[w][2] = p2; }
        __syncthreads();
        if (tid == 0) {
            float q0 = 0.f, q1 = 0.f, q2 = 0.f;
            for (int ww = 0; ww < 8; ww++) {
                q0 += sred[ww][0]; q1 += sred[ww][1]; q2 += sred[ww][2];
            }
            gF[j] = make_float2(q0, q1);
            gfb[j] = q2 + fc1_b[j];
        }
    }
}

// ---------------------------------------------------------------------------
// Main kernel: one block per batch; 512 threads; warp w owns points
// [64w, 64w+64) for the MMA stage; thread t owns points t, t+512 for the
// softmax stage (scores passed through shared sScore).
// ---------------------------------------------------------------------------
__global__ void __launch_bounds__(BT, 2)
attn_kernel(const float* __restrict__ stat, const float* __restrict__ dyn,
            const float* __restrict__ istate,
            const float* __restrict__ fc2_w, const float* __restrict__ fc2_b,
            float* __restrict__ out)
{
    __shared__ uint2 sU[NS];         // per-point features {(x0,x1),(y0,y1)} f16
    __shared__ unsigned sBf[NH * 4]; // per-h B-frag half2s {(A0,A1),(B0,B1),0,0}
    __shared__ uint2 sGV[NH / 2];    // per h-pair {(g,g'), (v,v')} f16
    __shared__ float4 sCdv[NH];      // (C0,C1,d,v) f32
    __shared__ float sScore[NS];     // scores handoff
    __shared__ float sredM[16], sredP[16], sredX[16], sredY[16];
    __shared__ float bc[4];

    const float LOG2E = 1.4426950408889634f;
    int b = blockIdx.x;
    int s = threadIdx.x;              // 0..511
    int lane = s & 31, warp = s >> 5;
    int gid = lane >> 2, tig = lane & 3;

    // odd-quintic tanh: tanh(x) ~= x*(1 + x2*(PA + PB*x2))
    const unsigned PA2 = f2h2(-0.3248f, -0.3248f);
    const unsigned PB2 = f2h2(0.0864f, 0.0864f);
    const unsigned ONE2 = f2h2(1.0f, 1.0f);

    // features for points s (lo) and s+512 (hi); f32 masters for softmax
    float x0l = stat[b * 2 * NS + s],      x0h = stat[b * 2 * NS + s + BT];
    float x1l = stat[b * 2 * NS + NS + s], x1h = stat[b * 2 * NS + NS + s + BT];
    float y0l = dyn[b * 2 * NS + s],       y0h = dyn[b * 2 * NS + s + BT];
    float y1l = dyn[b * 2 * NS + NS + s],  y1h = dyn[b * 2 * NS + NS + s + BT];

    // shared feature table (f16) for A-fragments
    sU[s]      = make_uint2(f2h2(x0l, x1l), f2h2(y0l, y1l));
    sU[s + BT] = make_uint2(f2h2(x0h, x1h), f2h2(y0h, y1h));

    if (s < NH) {
        sCdv[s] = gCdv[s];
        float4 q = gABp[s];
        sBf[s * 4 + 0] = f2h2(q.x, q.y);   // (A0, A1)
        sBf[s * 4 + 1] = f2h2(q.z, q.w);   // (B0, B1)
        sBf[s * 4 + 2] = 0u;               // k-pad
        sBf[s * 4 + 3] = 0u;
    }
    __syncthreads();

    // A fragments: constant across iterations and h-tiles.
    // pt-tile p covers points warp*64 + p*16 + {0..15}.
    unsigned a01[4], a23[4];
    #pragma unroll
    for (int p = 0; p < 4; p++) {
        int pt0 = (warp << 6) + (p << 4) + gid;
        uint2 F0 = sU[pt0];
        uint2 F1 = sU[pt0 + 8];
        a01[p] = (tig == 0) ? F0.x : (tig == 1) ? F0.y : 0u;
        a23[p] = (tig == 0) ? F1.x : (tig == 1) ? F1.y : 0u;
    }

    float z0 = istate[b * 2 + 0];
    float z1 = istate[b * 2 + 1];

    for (int it = 0; it < NITER; it++) {
        __syncthreads();
        if (s < NH / 2) {
            float4 ca = sCdv[2 * s];
            float4 cb = sCdv[2 * s + 1];
            float ga = fmaf(ca.x, z0, fmaf(ca.y, z1, ca.z));
            float gb = fmaf(cb.x, z0, fmaf(cb.y, z1, cb.z));
            sGV[s] = make_uint2(f2h2(ga, gb), f2h2(ca.w, cb.w));
        }
        __syncthreads();

        // MMA mainloop: 32 h-tiles of 8 h; 4 pt-tiles of 16 points per warp.
        // ht%4==0: MUFU tanh16x2; else FMA-pipe quintic (f=3/4).
        // v-accumulation: chained f32-acc MMA (th frag reused as A frag).
        float acc[4][4];
        #pragma unroll
        for (int p = 0; p < 4; p++)
            #pragma unroll
            for (int i = 0; i < 4; i++) acc[p][i] = 0.f;

        #pragma unroll
        for (int ht = 0; ht < 32; ht++) {
            unsigned bf = sBf[((ht << 3) + gid) * 4 + tig];     // arg B frag
            uint2 gv = sGV[(ht << 2) + tig];                    // {(g,g'),(v,v')}
            // acc-MMA B frag: column 0 = v of this tile's 8 h, others 0
            unsigned bacc = (gid == 0) ? gv.y : 0u;
            #pragma unroll
            for (int p = 0; p < 4; p++) {
                unsigned d0, d1;
                mma16n8k8(d0, d1, a01[p], a23[p], bf, gv.x, gv.x);
                unsigned th0, th1;
                if ((ht & 3) == 0) {
                    th0 = tanh16x2(d0);
                    th1 = tanh16x2(d1);
                } else {
                    unsigned x20 = hmul2u(d0, d0);
                    unsigned u0  = hfma2u(x20, PB2, PA2);
                    unsigned w0  = hfma2u(u0, x20, ONE2);
                    th0 = hmul2u(w0, d0);
                    unsigned x21 = hmul2u(d1, d1);
                    unsigned u1  = hfma2u(x21, PB2, PA2);
                    unsigned w1  = hfma2u(u1, x21, ONE2);
                    th1 = hmul2u(w1, d1);
                }
                mma16n8k8_f32(acc[p], th0, th1, bacc);
            }
        }

        // scores: column 0 of the f32 accumulator, held by tig==0 threads.
        if (tig == 0) {
            #pragma unroll
            for (int p = 0; p < 4; p++) {
                int pt0 = (warp << 6) + (p << 4) + gid;
                sScore[pt0]     = acc[p][0];   // row gid,   col 0
                sScore[pt0 + 8] = acc[p][2];   // row gid+8, col 0
            }
        }
        __syncthreads();

        float t0 = sScore[s];
        float t1 = sScore[s + BT];

        // ---- R9 softmax stage (verbatim) ----
        float m = fmaxf(t0, t1);
        #pragma unroll
        for (int o = 16; o > 0; o >>= 1)
            m = fmaxf(m, __shfl_xor_sync(0xffffffffu, m, o));
        if (lane == 0) sredM[warp] = m;
        __syncthreads();
        if (s < 16) {
            float mm = sredM[s];
            #pragma unroll
            for (int o = 8; o > 0; o >>= 1)
                mm = fmaxf(mm, __shfl_xor_sync(0xffffu, mm, o));
            if (s == 0) bc[0] = mm;
        }
        __syncthreads();
        float M = bc[0];

        float p0 = ex2_approx((t0 - M) * LOG2E);
        float p1 = ex2_approx((t1 - M) * LOG2E);
        float a  = p0 + p1;
        float bx = fmaf(p0, x0l, p1 * x0h);
        float by = fmaf(p0, x1l, p1 * x1h);
        #pragma unroll
        for (int o = 16; o > 0; o >>= 1) {
            a  += __shfl_xor_sync(0xffffffffu, a,  o);
            bx += __shfl_xor_sync(0xffffffffu, bx, o);
            by += __shfl_xor_sync(0xffffffffu, by, o);
        }
        if (lane == 0) { sredP[warp] = a; sredX[warp] = bx; sredY[warp] = by; }
        __syncthreads();
        if (s < 16) {
            float aa = sredP[s], xx = sredX[s], yy = sredY[s];
            #pragma unroll
            for (int o = 8; o > 0; o >>= 1) {
                aa += __shfl_xor_sync(0xffffu, aa, o);
                xx += __shfl_xor_sync(0xffffu, xx, o);
                yy += __shfl_xor_sync(0xffffu, yy, o);
            }
            if (s == 0) { bc[1] = aa; bc[2] = xx; bc[3] = yy; }
        }
        __syncthreads();
        float inv = 1.f / bc[1];
        z0 = bc[2] * inv;   // xbar0
        z1 = bc[3] * inv;   // xbar1
    }

    // Output MLP (folded through sw), f32
    if (s == 0) {
        float o = fc2_b[0];
        #pragma unroll
        for (int j = 0; j < NFC; j++) {
            float hv = fmaf(gF[j].x, z0, fmaf(gF[j].y, z1, gfb[j]));
            hv = fmaxf(hv, 0.f);
            o = fmaf(fc2_w[j], hv, o);
        }
        out[b] = o;
    }
}

extern "C" void kernel_launch(void* const* d_in, const int* in_sizes, int n_in,
                              void* d_out, int out_size)
{
    const float* stat   = (const float*)d_in[0];   // [256, 2, 1024]
    const float* dyn    = (const float*)d_in[1];   // [256, 2, 1024]
    const float* istate = (const float*)d_in[2];   // [256, 2]
    const float* sw     = (const float*)d_in[3];   // [256, 2]
    const float* sb     = (const float*)d_in[4];   // [256]
    const float* dw     = (const float*)d_in[5];   // [256, 2]
    const float* db     = (const float*)d_in[6];   // [256]
    const float* v      = (const float*)d_in[7];   // [1, 256]
    const float* W      = (const float*)d_in[8];   // [256, 768]
    const float* fc1_w  = (const float*)d_in[9];   // [20, 256]
    const float* fc1_b  = (const float*)d_in[10];  // [20]
    const float* fc2_w  = (const float*)d_in[11];  // [1, 20]
    const float* fc2_b  = (const float*)d_in[12];  // [1]
    float* out = (float*)d_out;                    // [256, 1]

    precompute_kernel<<<NH + NFC, 256>>>(sw, sb, dw, db, W, v, fc1_w, fc1_b);
    attn_kernel<<<NB, BT>>>(stat, dyn, istate, fc2_w, fc2_b, out);
}